// round 16
// baseline (speedup 1.0000x reference)
#include <cuda_runtime.h>
#include <cuda_bf16.h>
#include <math.h>
#include <stdint.h>

// ----------------------------------------------------------------------------
// IGNN / EGNN layer, GB300 (sm_103a built as sm_103 -> mma.sync, no tcgen05).
// Round 16: edge kernel occupancy push — accumulator chunking (dacc/dd 64->8
// regs via per-ntp fusion; silu outputs staged bf16 through the dead C region
// for the post-attention scatter), 7 warps/CTA, smem 75008B -> 3 CTAs/SM
// (21 warps/SM, +31% on a latency-bound kernel).
// Node kernels unchanged from R15.
// ----------------------------------------------------------------------------

#define NN 50000
#define NE 800000
#define DH 128
#define DE 16
#define DM 128

__device__ __align__(16) float g_Ha[(size_t)NN * DM];
__device__ __align__(16) float g_Hb[(size_t)NN * DM];
__device__ __align__(16) float g_msg[(size_t)NN * DM];

__device__ __forceinline__ float fsigmoid(float v) {
    float t;
    asm("tanh.approx.f32 %0, %1;" : "=f"(t) : "f"(v * 0.5f));
    return fmaf(0.5f, t, 0.5f);
}

__device__ __forceinline__ uint32_t smem_to_u32(const void* smem_ptr) {
    uint32_t addr;
    asm("{ .reg .u64 tmp; cvta.to.shared.u64 tmp, %1; cvt.u32.u64 %0, tmp; }"
        : "=r"(addr) : "l"(smem_ptr));
    return addr;
}

__device__ __forceinline__ void ldmatrix_x4(uint32_t& r0, uint32_t& r1,
                                            uint32_t& r2, uint32_t& r3, uint32_t addr) {
    asm volatile("ldmatrix.sync.aligned.m8n8.x4.shared.b16 {%0,%1,%2,%3}, [%4];"
                 : "=r"(r0), "=r"(r1), "=r"(r2), "=r"(r3) : "r"(addr));
}
__device__ __forceinline__ void mma_bf16(float d[4], const uint32_t a[4],
                                         const uint32_t b[2], const float c[4]) {
    asm volatile(
        "mma.sync.aligned.m16n8k16.row.col.f32.bf16.bf16.f32 "
        "{%0,%1,%2,%3}, {%4,%5,%6,%7}, {%8,%9}, {%10,%11,%12,%13};"
        : "=f"(d[0]), "=f"(d[1]), "=f"(d[2]), "=f"(d[3])
        : "r"(a[0]), "r"(a[1]), "r"(a[2]), "r"(a[3]),
          "r"(b[0]), "r"(b[1]),
          "f"(c[0]), "f"(c[1]), "f"(c[2]), "f"(c[3]));
}
__device__ __forceinline__ void red_v4(float* addr, float v0, float v1, float v2, float v3) {
    asm volatile("red.global.add.v4.f32 [%0], {%1, %2, %3, %4};"
                 :: "l"(addr), "f"(v0), "f"(v1), "f"(v2), "f"(v3) : "memory");
}

__device__ __forceinline__ uint2 pack_bf16x4(float4 v) {
    __nv_bfloat162 lo = __floats2bfloat162_rn(v.x, v.y);
    __nv_bfloat162 hi = __floats2bfloat162_rn(v.z, v.w);
    uint2 r;
    r.x = *(uint32_t*)&lo;
    r.y = *(uint32_t*)&hi;
    return r;
}
__device__ __forceinline__ uint32_t pack_bf16x2(float a, float b) {
    __nv_bfloat162 p = __floats2bfloat162_rn(a, b);
    return *(uint32_t*)&p;
}
__device__ __forceinline__ float2 unpack_bf16x2(uint32_t w) {
    __nv_bfloat162 p = *(__nv_bfloat162*)&w;
    return make_float2(__bfloat162float(p.x), __bfloat162float(p.y));
}

// ---------------------------------------------------------------------------
// kernel 1 (HMMA): Ha = h @ W1a^T, Hb = h @ W1b^T + g_msg zeroing.  (R15)
// ---------------------------------------------------------------------------
#define NP_A   0
#define NP_WA  34816
#define NP_WB  69632
#define NP_TOTAL 104448
#define RS 272

__global__ void __launch_bounds__(256, 2)
node_pre_kernel(const float* __restrict__ h, const float* __restrict__ We1) {
    extern __shared__ __align__(16) char smraw[];
    const uint32_t smem_u32 = smem_to_u32(smraw);
    const int tid  = threadIdx.x;
    const int warp = tid >> 5;
    const int lane = tid & 31;

    for (int idx = tid; idx < 128 * 128; idx += 256) {
        int n = idx >> 7, k = idx & 127;
        *(__nv_bfloat16*)(smraw + NP_WA + n * RS + k * 2) =
            __float2bfloat16(We1[n * 273 + k]);
        *(__nv_bfloat16*)(smraw + NP_WB + n * RS + k * 2) =
            __float2bfloat16(We1[n * 273 + 128 + k]);
    }
    __syncthreads();

    const int m0 = warp * 16;
    const int arow = m0 + (lane & 7) + ((lane >> 3) & 1) * 8;
    const uint32_t a_base  = smem_u32 + NP_A + (uint32_t)arow * RS + ((lane >> 4) & 1) * 16;
    const uint32_t ba4_base = smem_u32 + NP_WA
                            + (uint32_t)((lane & 7) + ((lane >> 4) & 1) * 8) * RS
                            + ((lane >> 3) & 1) * 16;
    const uint32_t bb4_base = ba4_base + (NP_WB - NP_WA);

    const int tig = lane & 3, grp = lane >> 2;
    const int ntiles = (NN + 127) / 128;

    for (int tile = blockIdx.x; tile < ntiles; tile += gridDim.x) {
        const int base = tile * 128;
        __syncthreads();
        for (int idx = tid; idx < 128 * 32; idx += 256) {
            int r = idx >> 5, j4 = (idx & 31) * 4;
            int node = base + r;
            float4 v = make_float4(0.f, 0.f, 0.f, 0.f);
            if (node < NN) {
                v = *(const float4*)&h[(size_t)node * DH + j4];
                *(float4*)&g_msg[(size_t)node * DM + j4] = make_float4(0.f, 0.f, 0.f, 0.f);
            }
            *(uint2*)(smraw + NP_A + r * RS + j4 * 2) = pack_bf16x4(v);
        }
        __syncthreads();

        const int node0 = base + m0 + grp;
        const int node1 = node0 + 8;

        uint32_t afr[8][4];
#pragma unroll
        for (int k = 0; k < 8; k++)
            ldmatrix_x4(afr[k][0], afr[k][1], afr[k][2], afr[k][3],
                        a_base + (uint32_t)k * 32);

        float acc[16][4];

#pragma unroll
        for (int nt = 0; nt < 16; nt++)
#pragma unroll
            for (int r = 0; r < 4; r++) acc[nt][r] = 0.f;
#pragma unroll
        for (int k = 0; k < 8; k++) {
#pragma unroll
            for (int ntp = 0; ntp < 8; ntp++) {
                uint32_t b4[4];
                ldmatrix_x4(b4[0], b4[1], b4[2], b4[3],
                            ba4_base + (uint32_t)ntp * (16 * RS) + (uint32_t)k * 32);
                mma_bf16(acc[2 * ntp],     afr[k], b4,     acc[2 * ntp]);
                mma_bf16(acc[2 * ntp + 1], afr[k], b4 + 2, acc[2 * ntp + 1]);
            }
        }
#pragma unroll
        for (int nt = 0; nt < 16; nt++) {
            const int c0 = nt * 8 + tig * 2;
            if (node0 < NN) *(float2*)&g_Ha[(size_t)node0 * DM + c0] =
                make_float2(acc[nt][0], acc[nt][1]);
            if (node1 < NN) *(float2*)&g_Ha[(size_t)node1 * DM + c0] =
                make_float2(acc[nt][2], acc[nt][3]);
        }

#pragma unroll
        for (int nt = 0; nt < 16; nt++)
#pragma unroll
            for (int r = 0; r < 4; r++) acc[nt][r] = 0.f;
#pragma unroll
        for (int k = 0; k < 8; k++) {
#pragma unroll
            for (int ntp = 0; ntp < 8; ntp++) {
                uint32_t b4[4];
                ldmatrix_x4(b4[0], b4[1], b4[2], b4[3],
                            bb4_base + (uint32_t)ntp * (16 * RS) + (uint32_t)k * 32);
                mma_bf16(acc[2 * ntp],     afr[k], b4,     acc[2 * ntp]);
                mma_bf16(acc[2 * ntp + 1], afr[k], b4 + 2, acc[2 * ntp + 1]);
            }
        }
#pragma unroll
        for (int nt = 0; nt < 16; nt++) {
            const int c0 = nt * 8 + tig * 2;
            if (node0 < NN) *(float2*)&g_Hb[(size_t)node0 * DM + c0] =
                make_float2(acc[nt][0], acc[nt][1]);
            if (node1 < NN) *(float2*)&g_Hb[(size_t)node1 * DM + c0] =
                make_float2(acc[nt][2], acc[nt][3]);
        }
    }
}

// ---------------------------------------------------------------------------
// kernel 2: edge kernel — 7 warps/CTA, 3 CTAs/SM, chunked accumulators.
//
// SMEM bytes:
//   [0]      C    : 7 warps x (16 rows x 136 bf16, stride 272B) = 30464
//   [30464]  EA   : 7 warps x 512B                              = 3584
//   [34048]  W2   : 128 x 136 bf16 (stride 272)                 = 34816
//   [68864]  W1E  : 128 x 16 bf16 (stride 32)                   = 4096
//   [72960]  Wr / [73472] be1s / [73984] be2s / [74496] Was : 128 f32 each
//   total 75008 B -> 3 CTAs/SM (225024 <= 228KB)
// ---------------------------------------------------------------------------
#define EB_C     0
#define EB_EA    30464
#define EB_W2    34048
#define EB_W1E   68864
#define EB_WR    72960
#define EB_BE1   73472
#define EB_BE2   73984
#define EB_WAS   74496
#define EB_TOTAL 75008

#define CSTRIDE 272
#define WARP_C_BYTES (16 * CSTRIDE)
#define WARP_EA_BYTES 512
#define EW 7           // warps per edge CTA
#define ET 224         // threads per edge CTA

__global__ void __launch_bounds__(ET, 3)
edge_kernel(const float* __restrict__ x,
            const float* __restrict__ edge_attr,
            const float* __restrict__ We1,
            const float* __restrict__ be1,
            const float* __restrict__ We2,
            const float* __restrict__ be2,
            const float* __restrict__ Wa,
            const float* __restrict__ ba,
            const int* __restrict__ ei) {
    extern __shared__ __align__(16) char smraw[];
    float* Wr   = (float*)(smraw + EB_WR);
    float* be1s = (float*)(smraw + EB_BE1);
    float* be2s = (float*)(smraw + EB_BE2);
    float* Was  = (float*)(smraw + EB_WAS);

    const uint32_t smem_u32 = smem_to_u32(smraw);
    const int tid  = threadIdx.x;
    const int warp = tid >> 5;
    const int lane = tid & 31;

    // ---- preamble ----
    for (int idx = tid; idx < 128 * 128; idx += ET) {
        int n = idx >> 7, k = idx & 127;
        *(__nv_bfloat16*)(smraw + EB_W2 + n * CSTRIDE + k * 2) =
            __float2bfloat16(We2[n * 128 + k]);
    }
    for (int idx = tid; idx < 128 * 16; idx += ET) {
        int n = idx >> 4, t = idx & 15;
        *(__nv_bfloat16*)(smraw + EB_W1E + n * 32 + t * 2) =
            __float2bfloat16(We1[n * 273 + 257 + t]);
    }
    for (int k = tid; k < 128; k += ET) {
        Wr[k]   = We1[k * 273 + 256];
        be1s[k] = be1[k];
        be2s[k] = be2[k];
        Was[k]  = Wa[k];
    }
    const float ba0 = ba[0];
    __syncthreads();

    const uint32_t c_region  = smem_u32 + EB_C  + (uint32_t)warp * WARP_C_BYTES;
    const uint32_t ea_region = smem_u32 + EB_EA + (uint32_t)warp * WARP_EA_BYTES;

    const int tig = lane & 3, grp = lane >> 2;
    const uint32_t c_fr0 = c_region + (uint32_t)grp * CSTRIDE + (uint32_t)tig * 4;
    const uint32_t c_fr1 = c_fr0 + 8 * CSTRIDE;
    const uint32_t ea_lm = ea_region + (uint32_t)(lane & 15) * 32 + ((lane >> 4) & 1) * 16;
    const uint32_t w1e4_base = smem_u32 + EB_W1E
                             + (uint32_t)((lane & 7) + ((lane >> 4) & 1) * 8) * 32
                             + ((lane >> 3) & 1) * 16;
    const uint32_t b4_base = smem_u32 + EB_W2
                           + (uint32_t)((lane & 7) + ((lane >> 4) & 1) * 8) * CSTRIDE
                           + ((lane >> 3) & 1) * 16;

    const int jj = tig >> 1;
    const bool isOdd = (tig & 1) != 0;

    const int NWT = NE / 16;
    const int wstride = gridDim.x * EW;

    const float4 wr4  = *(const float4*)(Wr + lane * 4);
    const float4 be14 = *(const float4*)(be1s + lane * 4);

    for (int wt = blockIdx.x * EW + warp; wt < NWT; wt += wstride) {
        const int base = wt * 16;

        int rld = 0, cld = 0;
        float radld = 0.f;
        if (lane < 16) {
            rld = ei[base + lane];
            cld = ei[NE + base + lane];
            float dx = x[(size_t)rld * 3 + 0] - x[(size_t)cld * 3 + 0];
            float dy = x[(size_t)rld * 3 + 1] - x[(size_t)cld * 3 + 1];
            float dz = x[(size_t)rld * 3 + 2] - x[(size_t)cld * 3 + 2];
            radld = sqrtf(dx * dx + dy * dy + dz * dz);
        }

        // ---- coalesced gather: C[e] = Ha[row_e] + Hb[col_e] + rad*wr + be1 ----
#pragma unroll
        for (int e = 0; e < 16; e++) {
            const int   row  = __shfl_sync(0xFFFFFFFF, rld, e);
            const int   colN = __shfl_sync(0xFFFFFFFF, cld, e);
            const float rv   = __shfl_sync(0xFFFFFFFF, radld, e);
            float4 ha = *(const float4*)&g_Ha[(size_t)row  * DM + lane * 4];
            float4 hb = *(const float4*)&g_Hb[(size_t)colN * DM + lane * 4];
            float4 c;
            c.x = ha.x + hb.x + be14.x + rv * wr4.x;
            c.y = ha.y + hb.y + be14.y + rv * wr4.y;
            c.z = ha.z + hb.z + be14.z + rv * wr4.z;
            c.w = ha.w + hb.w + be14.w + rv * wr4.w;
            *(uint2*)(smraw + (c_region - smem_u32) + e * CSTRIDE + lane * 8) = pack_bf16x4(c);
        }
        {
            int e = lane >> 1, hf2 = lane & 1;
            const float4* pe = (const float4*)(edge_attr + (size_t)(base + e) * DE + hf2 * 8);
            float4 u0 = pe[0], u1 = pe[1];
            uint2 w0 = pack_bf16x4(u0), w1 = pack_bf16x4(u1);
            *(uint4*)(smraw + (ea_region - smem_u32) + e * 32 + hf2 * 16) =
                make_uint4(w0.x, w0.y, w1.x, w1.y);
        }
        __syncwarp();

        // ---- stage 1 (chunked): au[ntp] = silu(C + ea @ W1e^T) per ntp ----
        uint32_t au[8][4];
        {
            uint32_t aea[4];
            ldmatrix_x4(aea[0], aea[1], aea[2], aea[3], ea_lm);
#pragma unroll
            for (int ntp = 0; ntp < 8; ntp++) {
                float d0[4], d1[4];
                {
                    uint32_t lo0 = *(const uint32_t*)(smraw + (c_fr0 - smem_u32) + (2 * ntp) * 16);
                    uint32_t hi0 = *(const uint32_t*)(smraw + (c_fr1 - smem_u32) + (2 * ntp) * 16);
                    uint32_t lo1 = *(const uint32_t*)(smraw + (c_fr0 - smem_u32) + (2 * ntp + 1) * 16);
                    uint32_t hi1 = *(const uint32_t*)(smraw + (c_fr1 - smem_u32) + (2 * ntp + 1) * 16);
                    float2 f;
                    f = unpack_bf16x2(lo0); d0[0] = f.x; d0[1] = f.y;
                    f = unpack_bf16x2(hi0); d0[2] = f.x; d0[3] = f.y;
                    f = unpack_bf16x2(lo1); d1[0] = f.x; d1[1] = f.y;
                    f = unpack_bf16x2(hi1); d1[2] = f.x; d1[3] = f.y;
                }
                uint32_t b4[4];
                ldmatrix_x4(b4[0], b4[1], b4[2], b4[3], w1e4_base + (uint32_t)ntp * 512);
                mma_bf16(d0, aea, b4,     d0);
                mma_bf16(d1, aea, b4 + 2, d1);
                au[ntp][0] = pack_bf16x2(d0[0] * fsigmoid(d0[0]), d0[1] * fsigmoid(d0[1]));
                au[ntp][1] = pack_bf16x2(d0[2] * fsigmoid(d0[2]), d0[3] * fsigmoid(d0[3]));
                au[ntp][2] = pack_bf16x2(d1[0] * fsigmoid(d1[0]), d1[1] * fsigmoid(d1[1]));
                au[ntp][3] = pack_bf16x2(d1[2] * fsigmoid(d1[2]), d1[3] * fsigmoid(d1[3]));
            }
        }

        // ---- stage 2 (chunked): per ntp, K-loop MMA -> silu -> pr partial,
        //      s staged bf16 into C region (same-thread addresses) ----
        float pr0 = 0.f, pr1 = 0.f;
#pragma unroll
        for (int ntp = 0; ntp < 8; ntp++) {
            float d0[4], d1[4];
#pragma unroll
            for (int r = 0; r < 4; r++) { d0[r] = 0.f; d1[r] = 0.f; }
#pragma unroll
            for (int kk = 0; kk < 8; kk++) {
                uint32_t b4[4];
                ldmatrix_x4(b4[0], b4[1], b4[2], b4[3],
                            b4_base + (uint32_t)ntp * (16 * CSTRIDE) + (uint32_t)kk * 32);
                mma_bf16(d0, au[kk], b4,     d0);
                mma_bf16(d1, au[kk], b4 + 2, d1);
            }
            const int nt0 = 2 * ntp, nt1 = 2 * ntp + 1;
            {
                const int c0 = nt0 * 8 + tig * 2;
                float2 bb = *(float2*)&be2s[c0];
                float2 wa = *(float2*)&Was[c0];
                float v0 = d0[0] + bb.x, v1 = d0[1] + bb.y;
                float v2 = d0[2] + bb.x, v3 = d0[3] + bb.y;
                float s0 = v0 * fsigmoid(v0), s1 = v1 * fsigmoid(v1);
                float s2 = v2 * fsigmoid(v2), s3 = v3 * fsigmoid(v3);
                pr0 += s0 * wa.x + s1 * wa.y;
                pr1 += s2 * wa.x + s3 * wa.y;
                *(uint32_t*)(smraw + (c_fr0 - smem_u32) + nt0 * 16) = pack_bf16x2(s0, s1);
                *(uint32_t*)(smraw + (c_fr1 - smem_u32) + nt0 * 16) = pack_bf16x2(s2, s3);
            }
            {
                const int c0 = nt1 * 8 + tig * 2;
                float2 bb = *(float2*)&be2s[c0];
                float2 wa = *(float2*)&Was[c0];
                float v0 = d1[0] + bb.x, v1 = d1[1] + bb.y;
                float v2 = d1[2] + bb.x, v3 = d1[3] + bb.y;
                float s0 = v0 * fsigmoid(v0), s1 = v1 * fsigmoid(v1);
                float s2 = v2 * fsigmoid(v2), s3 = v3 * fsigmoid(v3);
                pr0 += s0 * wa.x + s1 * wa.y;
                pr1 += s2 * wa.x + s3 * wa.y;
                *(uint32_t*)(smraw + (c_fr0 - smem_u32) + nt1 * 16) = pack_bf16x2(s0, s1);
                *(uint32_t*)(smraw + (c_fr1 - smem_u32) + nt1 * 16) = pack_bf16x2(s2, s3);
            }
        }

        pr0 += __shfl_xor_sync(0xFFFFFFFF, pr0, 1);
        pr0 += __shfl_xor_sync(0xFFFFFFFF, pr0, 2);
        pr1 += __shfl_xor_sync(0xFFFFFFFF, pr1, 1);
        pr1 += __shfl_xor_sync(0xFFFFFFFF, pr1, 2);
        const float att0 = fsigmoid(pr0 + ba0);
        const float att1 = fsigmoid(pr1 + ba0);

        const int node0 = __shfl_sync(0xFFFFFFFF, rld, grp);
        const int node1 = __shfl_sync(0xFFFFFFFF, rld, grp + 8);
        const float attm = isOdd ? att1 : att0;
        float* dst = g_msg + (size_t)(isOdd ? node1 : node0) * DM + jj * 4;
#pragma unroll
        for (int nt = 0; nt < 16; nt++) {
            float2 f0 = unpack_bf16x2(*(const uint32_t*)(smraw + (c_fr0 - smem_u32) + nt * 16));
            float2 f1 = unpack_bf16x2(*(const uint32_t*)(smraw + (c_fr1 - smem_u32) + nt * 16));
            float s0 = f0.x, s1 = f0.y, s2 = f1.x, s3 = f1.y;
            float q0 = __shfl_xor_sync(0xFFFFFFFF, s0, 1);
            float q1 = __shfl_xor_sync(0xFFFFFFFF, s1, 1);
            float q2 = __shfl_xor_sync(0xFFFFFFFF, s2, 1);
            float q3 = __shfl_xor_sync(0xFFFFFFFF, s3, 1);
            float v0 = isOdd ? q2 : s0;
            float v1 = isOdd ? q3 : s1;
            float v2 = isOdd ? s2 : q0;
            float v3 = isOdd ? s3 : q1;
            red_v4(dst + nt * 8, v0 * attm, v1 * attm, v2 * attm, v3 * attm);
        }
        __syncwarp();   // all C/EA reads done before next iteration's writes
    }
}

// ---------------------------------------------------------------------------
// kernel 3 (HMMA): node post — 512 threads, warp-pair nt split.  (R15)
// ---------------------------------------------------------------------------
#define PO_A   0
#define PO_W1  67584
#define PO_W2  135168
#define PO_U   169984
#define PO_B1  204800
#define PO_B2  205312
#define PO_TOTAL 205824
#define RS2 528

__device__ __forceinline__ uint32_t silu_bf16x2(float a, float b) {
    const uint32_t HALF2 = 0x3F003F00u;
    uint32_t u = pack_bf16x2(a, b);
    uint32_t hu, t, sg, s;
    asm("mul.rn.bf16x2 %0, %1, %2;" : "=r"(hu) : "r"(u), "r"(HALF2));
    asm("tanh.approx.bf16x2 %0, %1;" : "=r"(t) : "r"(hu));
    asm("fma.rn.bf16x2 %0, %1, %2, %3;" : "=r"(sg) : "r"(t), "r"(HALF2), "r"(HALF2));
    asm("mul.rn.bf16x2 %0, %1, %2;" : "=r"(s) : "r"(u), "r"(sg));
    return s;
}

__global__ void __launch_bounds__(512, 1)
node_post_kernel(const float* __restrict__ h,
                 const float* __restrict__ Wh1,
                 const float* __restrict__ bh1,
                 const float* __restrict__ Wh2,
                 const float* __restrict__ bh2,
                 float* __restrict__ out) {
    extern __shared__ __align__(16) char smraw[];
    float* b1s = (float*)(smraw + PO_B1);
    float* b2s = (float*)(smraw + PO_B2);

    const uint32_t smem_u32 = smem_to_u32(smraw);
    const int tid  = threadIdx.x;
    const int warp = tid >> 5;
    const int lane = tid & 31;
    const int rg   = warp & 7;
    const int nh   = warp >> 3;

    for (int idx = tid; idx < 128 * 64; idx += 512) {
        int n = idx >> 6, k4 = (idx & 63) * 4;
        float4 v = *(const float4*)&Wh1[(size_t)n * 256 + k4];
        *(uint2*)(smraw + PO_W1 + n * RS2 + k4 * 2) = pack_bf16x4(v);
    }
    for (int idx = tid; idx < 128 * 32; idx += 512) {
        int n = idx >> 5, k4 = (idx & 31) * 4;
        float4 v = *(const float4*)&Wh2[(size_t)n * 128 + k4];
        *(uint2*)(smraw + PO_W2 + n * RS + k4 * 2) = pack_bf16x4(v);
    }
    for (int k = tid; k < 128; k += 512) {
        b1s[k] = bh1[k];
        b2s[k] = bh2[k];
    }
    __syncthreads();

    const int m0 = rg * 16;
    const int arow = m0 + (lane & 7) + ((lane >> 3) & 1) * 8;
    const uint32_t a1_base = smem_u32 + PO_A + (uint32_t)arow * RS2 + ((lane >> 4) & 1) * 16;
    const uint32_t a2_base = smem_u32 + PO_U + (uint32_t)arow * RS  + ((lane >> 4) & 1) * 16;
    const uint32_t b14_base = smem_u32 + PO_W1
                            + (uint32_t)((lane & 7) + ((lane >> 4) & 1) * 8) * RS2
                            + ((lane >> 3) & 1) * 16;
    const uint32_t b24_base = smem_u32 + PO_W2
                            + (uint32_t)((lane & 7) + ((lane >> 4) & 1) * 8) * RS
                            + ((lane >> 3) & 1) * 16;

    const int tig = lane & 3, grp = lane >> 2;
    const int ntiles = (NN + 127) / 128;

    for (int tile = blockIdx.x; tile < ntiles; tile += gridDim.x) {
        const int base = tile * 128;
        __syncthreads();
        for (int idx = tid; idx < 128 * 32; idx += 512) {
            int r = idx >> 5, j4 = (idx & 31) * 4;
            int node = base + r;
            float4 vh = (node < NN) ? *(const float4*)&h[(size_t)node * DH + j4]
                                    : make_float4(0.f, 0.f, 0.f, 0.f);
            float4 vm = (node < NN) ? *(const float4*)&g_msg[(size_t)node * DM + j4]
                                    : make_float4(0.f, 0.f, 0.f, 0.f);
            *(uint2*)(smraw + PO_A + r * RS2 + j4 * 2)         = pack_bf16x4(vh);
            *(uint2*)(smraw + PO_A + r * RS2 + 256 + j4 * 2)   = pack_bf16x4(vm);
        }
        __syncthreads();

        float acc[8][4];
#pragma unroll
        for (int nt = 0; nt < 8; nt++)
#pragma unroll
            for (int r = 0; r < 4; r++) acc[nt][r] = 0.f;
#pragma unroll
        for (int k = 0; k < 16; k++) {
            uint32_t a[4];
            ldmatrix_x4(a[0], a[1], a[2], a[3], a1_base + (uint32_t)k * 32);
#pragma unroll
            for (int p = 0; p < 4; p++) {
                uint32_t b4[4];
                ldmatrix_x4(b4[0], b4[1], b4[2], b4[3],
                            b14_base + (uint32_t)(nh * 4 + p) * (16 * RS2) + (uint32_t)k * 32);
                mma_bf16(acc[2 * p],     a, b4,     acc[2 * p]);
                mma_bf16(acc[2 * p + 1], a, b4 + 2, acc[2 * p + 1]);
            }
        }
#pragma unroll
        for (int ntl = 0; ntl < 8; ntl++) {
            const int c0 = (nh * 8 + ntl) * 8 + tig * 2;
            float2 bb = *(float2*)&b1s[c0];
            uint32_t q0 = silu_bf16x2(acc[ntl][0] + bb.x, acc[ntl][1] + bb.y);
            uint32_t q1 = silu_bf16x2(acc[ntl][2] + bb.x, acc[ntl][3] + bb.y);
            *(uint32_t*)(smraw + PO_U + (m0 + grp) * RS + c0 * 2)     = q0;
            *(uint32_t*)(smraw + PO_U + (m0 + grp + 8) * RS + c0 * 2) = q1;
        }
        __syncthreads();

#pragma unroll
        for (int nt = 0; nt < 8; nt++)
#pragma unroll
            for (int r = 0; r < 4; r++) acc[nt][r] = 0.f;
#pragma unroll
        for (int k = 0; k < 8; k++) {
            uint32_t a[4];
            ldmatrix_x4(a[0], a[1], a[2], a[3], a2_base + (uint32_t)k * 32);
#pragma unroll
            for (int p = 0; p < 4; p++) {
                uint32_t b4[4];
                ldmatrix_x4(b4[0], b4[1], b4[2], b4[3],
                            b24_base + (uint32_t)(nh * 4 + p) * (16 * RS) + (uint32_t)k * 32);
                mma_bf16(acc[2 * p],     a, b4,     acc[2 * p]);
                mma_bf16(acc[2 * p + 1], a, b4 + 2, acc[2 * p + 1]);
            }
        }

        const int node0 = base + m0 + grp;
        const int node1 = node0 + 8;
#pragma unroll
        for (int ntl = 0; ntl < 8; ntl++) {
            const int c0 = (nh * 8 + ntl) * 8 + tig * 2;
            float2 bb = *(float2*)&b2s[c0];
            if (node0 < NN) {
                float2 hv = *(const float2*)&h[(size_t)node0 * DH + c0];
                *(float2*)&out[(size_t)node0 * DH + c0] =
                    make_float2(hv.x + acc[ntl][0] + bb.x, hv.y + acc[ntl][1] + bb.y);
            }
            if (node1 < NN) {
                float2 hv = *(const float2*)&h[(size_t)node1 * DH + c0];
                *(float2*)&out[(size_t)node1 * DH + c0] =
                    make_float2(hv.x + acc[ntl][2] + bb.x, hv.y + acc[ntl][3] + bb.y);
            }
        }
    }
}

// ---------------------------------------------------------------------------
extern "C" void kernel_launch(void* const* d_in, const int* in_sizes, int n_in,
                              void* d_out, int out_size) {
    const float* x   = (const float*)d_in[0];
    const float* h   = (const float*)d_in[1];
    const float* ea  = (const float*)d_in[2];
    const float* We1 = (const float*)d_in[3];
    const float* be1 = (const float*)d_in[4];
    const float* We2 = (const float*)d_in[5];
    const float* be2 = (const float*)d_in[6];
    const float* Wh1 = (const float*)d_in[7];
    const float* bh1 = (const float*)d_in[8];
    const float* Wh2 = (const float*)d_in[9];
    const float* bh2 = (const float*)d_in[10];
    const float* Wa  = (const float*)d_in[11];
    const float* ba  = (const float*)d_in[12];
    const int*   ei  = (const int*)d_in[13];   // int32
    float* out = (float*)d_out;

    cudaFuncSetAttribute(node_pre_kernel,
                         cudaFuncAttributeMaxDynamicSharedMemorySize, NP_TOTAL);
    cudaFuncSetAttribute(edge_kernel,
                         cudaFuncAttributeMaxDynamicSharedMemorySize, EB_TOTAL);
    cudaFuncSetAttribute(node_post_kernel,
                         cudaFuncAttributeMaxDynamicSharedMemorySize, PO_TOTAL);

    node_pre_kernel<<<296, 256, NP_TOTAL>>>(h, We1);   // also zeroes g_msg
    edge_kernel<<<444, ET, EB_TOTAL>>>(x, ea, We1, be1, We2, be2, Wa, ba, ei);
    node_post_kernel<<<148, 512, PO_TOTAL>>>(h, Wh1, bh1, Wh2, bh2, out);
}

// round 17
// speedup vs baseline: 1.0981x; 1.0981x over previous
#include <cuda_runtime.h>
#include <cuda_bf16.h>
#include <math.h>
#include <stdint.h>

// ----------------------------------------------------------------------------
// IGNN / EGNN layer, GB300 (sm_103a built as sm_103 -> mma.sync, no tcgen05).
// Round 17 (FINAL): revert to R15 — the measured optimum of this session.
// R16's 3-CTA/chunked-accumulator variant regressed (serialized stage-2 MMA
// chains killed intra-warp ILP); R15's 8-wide independent accumulator chains
// at 2 CTAs/SM is the proven balance point.
//
// Structure: decomposed e_in@We1^T (Ha/Hb per node), all GEMMs on bf16
// m16n8k16 mma.sync, warp-autonomous edge tiles, coalesced row-major
// gathers, tanh.approx sigmoid, red.global.add.v4.f32 scatter.
// ----------------------------------------------------------------------------

#define NN 50000
#define NE 800000
#define DH 128
#define DE 16
#define DM 128

__device__ __align__(16) float g_Ha[(size_t)NN * DM];
__device__ __align__(16) float g_Hb[(size_t)NN * DM];
__device__ __align__(16) float g_msg[(size_t)NN * DM];

// fp32 sigmoid via tanh.approx.f32 (1 MUFU)
__device__ __forceinline__ float fsigmoid(float v) {
    float t;
    asm("tanh.approx.f32 %0, %1;" : "=f"(t) : "f"(v * 0.5f));
    return fmaf(0.5f, t, 0.5f);
}

__device__ __forceinline__ uint32_t pack_bf16x2(float a, float b) {
    __nv_bfloat162 p = __floats2bfloat162_rn(a, b);
    return *(uint32_t*)&p;
}

// silu on a packed pair, entirely in bf16x2 (1 MUFU for 2 values).
__device__ __forceinline__ uint32_t silu_bf16x2(float a, float b) {
    const uint32_t HALF2 = 0x3F003F00u;   // (0.5, 0.5) bf16x2
    uint32_t u = pack_bf16x2(a, b);
    uint32_t hu, t, sg, s;
    asm("mul.rn.bf16x2 %0, %1, %2;" : "=r"(hu) : "r"(u), "r"(HALF2));
    asm("tanh.approx.bf16x2 %0, %1;" : "=r"(t) : "r"(hu));
    asm("fma.rn.bf16x2 %0, %1, %2, %3;" : "=r"(sg) : "r"(t), "r"(HALF2), "r"(HALF2));
    asm("mul.rn.bf16x2 %0, %1, %2;" : "=r"(s) : "r"(u), "r"(sg));
    return s;
}

__device__ __forceinline__ uint32_t smem_to_u32(const void* smem_ptr) {
    uint32_t addr;
    asm("{ .reg .u64 tmp; cvta.to.shared.u64 tmp, %1; cvt.u32.u64 %0, tmp; }"
        : "=r"(addr) : "l"(smem_ptr));
    return addr;
}

__device__ __forceinline__ void ldmatrix_x4(uint32_t& r0, uint32_t& r1,
                                            uint32_t& r2, uint32_t& r3, uint32_t addr) {
    asm volatile("ldmatrix.sync.aligned.m8n8.x4.shared.b16 {%0,%1,%2,%3}, [%4];"
                 : "=r"(r0), "=r"(r1), "=r"(r2), "=r"(r3) : "r"(addr));
}
__device__ __forceinline__ void mma_bf16(float d[4], const uint32_t a[4],
                                         const uint32_t b[2], const float c[4]) {
    asm volatile(
        "mma.sync.aligned.m16n8k16.row.col.f32.bf16.bf16.f32 "
        "{%0,%1,%2,%3}, {%4,%5,%6,%7}, {%8,%9}, {%10,%11,%12,%13};"
        : "=f"(d[0]), "=f"(d[1]), "=f"(d[2]), "=f"(d[3])
        : "r"(a[0]), "r"(a[1]), "r"(a[2]), "r"(a[3]),
          "r"(b[0]), "r"(b[1]),
          "f"(c[0]), "f"(c[1]), "f"(c[2]), "f"(c[3]));
}
__device__ __forceinline__ void red_v4(float* addr, float v0, float v1, float v2, float v3) {
    asm volatile("red.global.add.v4.f32 [%0], {%1, %2, %3, %4};"
                 :: "l"(addr), "f"(v0), "f"(v1), "f"(v2), "f"(v3) : "memory");
}

__device__ __forceinline__ uint2 pack_bf16x4(float4 v) {
    __nv_bfloat162 lo = __floats2bfloat162_rn(v.x, v.y);
    __nv_bfloat162 hi = __floats2bfloat162_rn(v.z, v.w);
    uint2 r;
    r.x = *(uint32_t*)&lo;
    r.y = *(uint32_t*)&hi;
    return r;
}
__device__ __forceinline__ float2 unpack_bf16x2(uint32_t w) {
    __nv_bfloat162 p = *(__nv_bfloat162*)&w;
    return make_float2(__bfloat162float(p.x), __bfloat162float(p.y));
}

// ---------------------------------------------------------------------------
// kernel 1 (HMMA): Ha = h @ W1a^T, Hb = h @ W1b^T + g_msg zeroing.
// A-fragments cached across both GEMMs; B via x4 nt-pairs.
// ---------------------------------------------------------------------------
#define NP_A   0
#define NP_WA  34816
#define NP_WB  69632
#define NP_TOTAL 104448
#define RS 272

__global__ void __launch_bounds__(256, 2)
node_pre_kernel(const float* __restrict__ h, const float* __restrict__ We1) {
    extern __shared__ __align__(16) char smraw[];
    const uint32_t smem_u32 = smem_to_u32(smraw);
    const int tid  = threadIdx.x;
    const int warp = tid >> 5;
    const int lane = tid & 31;

    for (int idx = tid; idx < 128 * 128; idx += 256) {
        int n = idx >> 7, k = idx & 127;
        *(__nv_bfloat16*)(smraw + NP_WA + n * RS + k * 2) =
            __float2bfloat16(We1[n * 273 + k]);
        *(__nv_bfloat16*)(smraw + NP_WB + n * RS + k * 2) =
            __float2bfloat16(We1[n * 273 + 128 + k]);
    }
    __syncthreads();

    const int m0 = warp * 16;
    const int arow = m0 + (lane & 7) + ((lane >> 3) & 1) * 8;
    const uint32_t a_base  = smem_u32 + NP_A + (uint32_t)arow * RS + ((lane >> 4) & 1) * 16;
    const uint32_t ba4_base = smem_u32 + NP_WA
                            + (uint32_t)((lane & 7) + ((lane >> 4) & 1) * 8) * RS
                            + ((lane >> 3) & 1) * 16;
    const uint32_t bb4_base = ba4_base + (NP_WB - NP_WA);

    const int tig = lane & 3, grp = lane >> 2;
    const int ntiles = (NN + 127) / 128;

    for (int tile = blockIdx.x; tile < ntiles; tile += gridDim.x) {
        const int base = tile * 128;
        __syncthreads();
        for (int idx = tid; idx < 128 * 32; idx += 256) {
            int r = idx >> 5, j4 = (idx & 31) * 4;
            int node = base + r;
            float4 v = make_float4(0.f, 0.f, 0.f, 0.f);
            if (node < NN) {
                v = *(const float4*)&h[(size_t)node * DH + j4];
                *(float4*)&g_msg[(size_t)node * DM + j4] = make_float4(0.f, 0.f, 0.f, 0.f);
            }
            *(uint2*)(smraw + NP_A + r * RS + j4 * 2) = pack_bf16x4(v);
        }
        __syncthreads();

        const int node0 = base + m0 + grp;
        const int node1 = node0 + 8;

        uint32_t afr[8][4];
#pragma unroll
        for (int k = 0; k < 8; k++)
            ldmatrix_x4(afr[k][0], afr[k][1], afr[k][2], afr[k][3],
                        a_base + (uint32_t)k * 32);

        float acc[16][4];

#pragma unroll
        for (int nt = 0; nt < 16; nt++)
#pragma unroll
            for (int r = 0; r < 4; r++) acc[nt][r] = 0.f;
#pragma unroll
        for (int k = 0; k < 8; k++) {
#pragma unroll
            for (int ntp = 0; ntp < 8; ntp++) {
                uint32_t b4[4];
                ldmatrix_x4(b4[0], b4[1], b4[2], b4[3],
                            ba4_base + (uint32_t)ntp * (16 * RS) + (uint32_t)k * 32);
                mma_bf16(acc[2 * ntp],     afr[k], b4,     acc[2 * ntp]);
                mma_bf16(acc[2 * ntp + 1], afr[k], b4 + 2, acc[2 * ntp + 1]);
            }
        }
#pragma unroll
        for (int nt = 0; nt < 16; nt++) {
            const int c0 = nt * 8 + tig * 2;
            if (node0 < NN) *(float2*)&g_Ha[(size_t)node0 * DM + c0] =
                make_float2(acc[nt][0], acc[nt][1]);
            if (node1 < NN) *(float2*)&g_Ha[(size_t)node1 * DM + c0] =
                make_float2(acc[nt][2], acc[nt][3]);
        }

#pragma unroll
        for (int nt = 0; nt < 16; nt++)
#pragma unroll
            for (int r = 0; r < 4; r++) acc[nt][r] = 0.f;
#pragma unroll
        for (int k = 0; k < 8; k++) {
#pragma unroll
            for (int ntp = 0; ntp < 8; ntp++) {
                uint32_t b4[4];
                ldmatrix_x4(b4[0], b4[1], b4[2], b4[3],
                            bb4_base + (uint32_t)ntp * (16 * RS) + (uint32_t)k * 32);
                mma_bf16(acc[2 * ntp],     afr[k], b4,     acc[2 * ntp]);
                mma_bf16(acc[2 * ntp + 1], afr[k], b4 + 2, acc[2 * ntp + 1]);
            }
        }
#pragma unroll
        for (int nt = 0; nt < 16; nt++) {
            const int c0 = nt * 8 + tig * 2;
            if (node0 < NN) *(float2*)&g_Hb[(size_t)node0 * DM + c0] =
                make_float2(acc[nt][0], acc[nt][1]);
            if (node1 < NN) *(float2*)&g_Hb[(size_t)node1 * DM + c0] =
                make_float2(acc[nt][2], acc[nt][3]);
        }
    }
}

// ---------------------------------------------------------------------------
// kernel 2: edge kernel — warp-autonomous, coalesced gather, full-HMMA,
// 8 warps/CTA, 2 CTAs/SM, wide independent accumulator chains (R15 optimum).
// ---------------------------------------------------------------------------
#define EB_C     0
#define EB_EA    34816
#define EB_W2    38912
#define EB_W1E   73728
#define EB_WR    77824
#define EB_BE1   78336
#define EB_BE2   78848
#define EB_WAS   79360
#define EB_TOTAL 79872

#define CSTRIDE 272
#define WARP_C_BYTES (16 * CSTRIDE)
#define WARP_EA_BYTES 512

__global__ void __launch_bounds__(256, 2)
edge_kernel(const float* __restrict__ x,
            const float* __restrict__ edge_attr,
            const float* __restrict__ We1,
            const float* __restrict__ be1,
            const float* __restrict__ We2,
            const float* __restrict__ be2,
            const float* __restrict__ Wa,
            const float* __restrict__ ba,
            const int* __restrict__ ei) {
    extern __shared__ __align__(16) char smraw[];
    float* Wr   = (float*)(smraw + EB_WR);
    float* be1s = (float*)(smraw + EB_BE1);
    float* be2s = (float*)(smraw + EB_BE2);
    float* Was  = (float*)(smraw + EB_WAS);

    const uint32_t smem_u32 = smem_to_u32(smraw);
    const int tid  = threadIdx.x;
    const int warp = tid >> 5;
    const int lane = tid & 31;

    for (int idx = tid; idx < 128 * 128; idx += 256) {
        int n = idx >> 7, k = idx & 127;
        *(__nv_bfloat16*)(smraw + EB_W2 + n * CSTRIDE + k * 2) =
            __float2bfloat16(We2[n * 128 + k]);
    }
    for (int idx = tid; idx < 128 * 16; idx += 256) {
        int n = idx >> 4, t = idx & 15;
        *(__nv_bfloat16*)(smraw + EB_W1E + n * 32 + t * 2) =
            __float2bfloat16(We1[n * 273 + 257 + t]);
    }
    for (int k = tid; k < 128; k += 256) {
        Wr[k]   = We1[k * 273 + 256];
        be1s[k] = be1[k];
        be2s[k] = be2[k];
        Was[k]  = Wa[k];
    }
    const float ba0 = ba[0];
    __syncthreads();

    const uint32_t c_region  = smem_u32 + EB_C  + (uint32_t)warp * WARP_C_BYTES;
    const uint32_t ea_region = smem_u32 + EB_EA + (uint32_t)warp * WARP_EA_BYTES;

    const int tig = lane & 3, grp = lane >> 2;
    const uint32_t c_fr0 = c_region + (uint32_t)grp * CSTRIDE + (uint32_t)tig * 4;
    const uint32_t c_fr1 = c_fr0 + 8 * CSTRIDE;
    const uint32_t ea_lm = ea_region + (uint32_t)(lane & 15) * 32 + ((lane >> 4) & 1) * 16;
    const uint32_t w1e4_base = smem_u32 + EB_W1E
                             + (uint32_t)((lane & 7) + ((lane >> 4) & 1) * 8) * 32
                             + ((lane >> 3) & 1) * 16;
    const uint32_t b4_base = smem_u32 + EB_W2
                           + (uint32_t)((lane & 7) + ((lane >> 4) & 1) * 8) * CSTRIDE
                           + ((lane >> 3) & 1) * 16;

    const int jj = tig >> 1;
    const bool isOdd = (tig & 1) != 0;

    const int NWT = NE / 16;
    const int wstride = gridDim.x * 8;

    const float4 wr4  = *(const float4*)(Wr + lane * 4);
    const float4 be14 = *(const float4*)(be1s + lane * 4);

    for (int wt = blockIdx.x * 8 + warp; wt < NWT; wt += wstride) {
        const int base = wt * 16;

        int rld = 0, cld = 0;
        float radld = 0.f;
        if (lane < 16) {
            rld = ei[base + lane];
            cld = ei[NE + base + lane];
            float dx = x[(size_t)rld * 3 + 0] - x[(size_t)cld * 3 + 0];
            float dy = x[(size_t)rld * 3 + 1] - x[(size_t)cld * 3 + 1];
            float dz = x[(size_t)rld * 3 + 2] - x[(size_t)cld * 3 + 2];
            radld = sqrtf(dx * dx + dy * dy + dz * dz);
        }

#pragma unroll
        for (int e = 0; e < 16; e++) {
            const int   row  = __shfl_sync(0xFFFFFFFF, rld, e);
            const int   colN = __shfl_sync(0xFFFFFFFF, cld, e);
            const float rv   = __shfl_sync(0xFFFFFFFF, radld, e);
            float4 ha = *(const float4*)&g_Ha[(size_t)row  * DM + lane * 4];
            float4 hb = *(const float4*)&g_Hb[(size_t)colN * DM + lane * 4];
            float4 c;
            c.x = ha.x + hb.x + be14.x + rv * wr4.x;
            c.y = ha.y + hb.y + be14.y + rv * wr4.y;
            c.z = ha.z + hb.z + be14.z + rv * wr4.z;
            c.w = ha.w + hb.w + be14.w + rv * wr4.w;
            *(uint2*)(smraw + (c_region - smem_u32) + e * CSTRIDE + lane * 8) = pack_bf16x4(c);
        }

        {
            int e = lane >> 1, hf2 = lane & 1;
            const float4* pe = (const float4*)(edge_attr + (size_t)(base + e) * DE + hf2 * 8);
            float4 u0 = pe[0], u1 = pe[1];
            uint2 w0 = pack_bf16x4(u0), w1 = pack_bf16x4(u1);
            *(uint4*)(smraw + (ea_region - smem_u32) + e * 32 + hf2 * 16) =
                make_uint4(w0.x, w0.y, w1.x, w1.y);
        }
        __syncwarp();

        float dacc[16][4];
#pragma unroll
        for (int nt = 0; nt < 16; nt++) {
            uint32_t lo = *(const uint32_t*)(smraw + (c_fr0 - smem_u32) + nt * 16);
            uint32_t hi = *(const uint32_t*)(smraw + (c_fr1 - smem_u32) + nt * 16);
            float2 f0 = unpack_bf16x2(lo);
            float2 f1 = unpack_bf16x2(hi);
            dacc[nt][0] = f0.x; dacc[nt][1] = f0.y;
            dacc[nt][2] = f1.x; dacc[nt][3] = f1.y;
        }
        {
            uint32_t aea[4];
            ldmatrix_x4(aea[0], aea[1], aea[2], aea[3], ea_lm);
#pragma unroll
            for (int ntp = 0; ntp < 8; ntp++) {
                uint32_t b4[4];
                ldmatrix_x4(b4[0], b4[1], b4[2], b4[3],
                            w1e4_base + (uint32_t)ntp * 512);
                mma_bf16(dacc[2 * ntp],     aea, b4,     dacc[2 * ntp]);
                mma_bf16(dacc[2 * ntp + 1], aea, b4 + 2, dacc[2 * ntp + 1]);
            }
        }
        __syncwarp();

        // stage-1 silu entirely in bf16x2 (m1 is bf16-destined)
        uint32_t au[8][4];
#pragma unroll
        for (int kk = 0; kk < 8; kk++) {
            float* d0 = dacc[2 * kk];
            float* d1 = dacc[2 * kk + 1];
            au[kk][0] = silu_bf16x2(d0[0], d0[1]);
            au[kk][1] = silu_bf16x2(d0[2], d0[3]);
            au[kk][2] = silu_bf16x2(d1[0], d1[1]);
            au[kk][3] = silu_bf16x2(d1[2], d1[3]);
        }

        float dd[16][4];
#pragma unroll
        for (int nt = 0; nt < 16; nt++)
#pragma unroll
            for (int r = 0; r < 4; r++) dd[nt][r] = 0.f;

#pragma unroll
        for (int kk = 0; kk < 8; kk++) {
#pragma unroll
            for (int ntp = 0; ntp < 8; ntp++) {
                uint32_t b4[4];
                ldmatrix_x4(b4[0], b4[1], b4[2], b4[3],
                            b4_base + (uint32_t)ntp * (16 * CSTRIDE) + (uint32_t)kk * 32);
                mma_bf16(dd[2 * ntp],     au[kk], b4,     dd[2 * ntp]);
                mma_bf16(dd[2 * ntp + 1], au[kk], b4 + 2, dd[2 * ntp + 1]);
            }
        }

        float pr0 = 0.f, pr1 = 0.f;
#pragma unroll
        for (int nt = 0; nt < 16; nt++) {
            const int c0 = nt * 8 + tig * 2;
            float2 bb = *(float2*)&be2s[c0];
            float2 wa = *(float2*)&Was[c0];
            float v0 = dd[nt][0] + bb.x;
            float v1 = dd[nt][1] + bb.y;
            float v2 = dd[nt][2] + bb.x;
            float v3 = dd[nt][3] + bb.y;
            float s0 = v0 * fsigmoid(v0);
            float s1 = v1 * fsigmoid(v1);
            float s2 = v2 * fsigmoid(v2);
            float s3 = v3 * fsigmoid(v3);
            dd[nt][0] = s0; dd[nt][1] = s1; dd[nt][2] = s2; dd[nt][3] = s3;
            pr0 += s0 * wa.x + s1 * wa.y;
            pr1 += s2 * wa.x + s3 * wa.y;
        }
        pr0 += __shfl_xor_sync(0xFFFFFFFF, pr0, 1);
        pr0 += __shfl_xor_sync(0xFFFFFFFF, pr0, 2);
        pr1 += __shfl_xor_sync(0xFFFFFFFF, pr1, 1);
        pr1 += __shfl_xor_sync(0xFFFFFFFF, pr1, 2);
        const float att0 = fsigmoid(pr0 + ba0);
        const float att1 = fsigmoid(pr1 + ba0);

        const int node0 = __shfl_sync(0xFFFFFFFF, rld, grp);
        const int node1 = __shfl_sync(0xFFFFFFFF, rld, grp + 8);
        const float attm = isOdd ? att1 : att0;
        float* dst = g_msg + (size_t)(isOdd ? node1 : node0) * DM + jj * 4;
#pragma unroll
        for (int nt = 0; nt < 16; nt++) {
            float s0 = dd[nt][0], s1 = dd[nt][1];
            float s2 = dd[nt][2], s3 = dd[nt][3];
            float q0 = __shfl_xor_sync(0xFFFFFFFF, s0, 1);
            float q1 = __shfl_xor_sync(0xFFFFFFFF, s1, 1);
            float q2 = __shfl_xor_sync(0xFFFFFFFF, s2, 1);
            float q3 = __shfl_xor_sync(0xFFFFFFFF, s3, 1);
            float v0 = isOdd ? q2 : s0;
            float v1 = isOdd ? q3 : s1;
            float v2 = isOdd ? s2 : q0;
            float v3 = isOdd ? s3 : q1;
            red_v4(dst + nt * 8, v0 * attm, v1 * attm, v2 * attm, v3 * attm);
        }
    }
}

// ---------------------------------------------------------------------------
// kernel 3 (HMMA): node post — 512 threads, warp-pair nt split, bf16x2 U-silu.
// ---------------------------------------------------------------------------
#define PO_A   0
#define PO_W1  67584
#define PO_W2  135168
#define PO_U   169984
#define PO_B1  204800
#define PO_B2  205312
#define PO_TOTAL 205824
#define RS2 528

__global__ void __launch_bounds__(512, 1)
node_post_kernel(const float* __restrict__ h,
                 const float* __restrict__ Wh1,
                 const float* __restrict__ bh1,
                 const float* __restrict__ Wh2,
                 const float* __restrict__ bh2,
                 float* __restrict__ out) {
    extern __shared__ __align__(16) char smraw[];
    float* b1s = (float*)(smraw + PO_B1);
    float* b2s = (float*)(smraw + PO_B2);

    const uint32_t smem_u32 = smem_to_u32(smraw);
    const int tid  = threadIdx.x;
    const int warp = tid >> 5;
    const int lane = tid & 31;
    const int rg   = warp & 7;
    const int nh   = warp >> 3;

    for (int idx = tid; idx < 128 * 64; idx += 512) {
        int n = idx >> 6, k4 = (idx & 63) * 4;
        float4 v = *(const float4*)&Wh1[(size_t)n * 256 + k4];
        *(uint2*)(smraw + PO_W1 + n * RS2 + k4 * 2) = pack_bf16x4(v);
    }
    for (int idx = tid; idx < 128 * 32; idx += 512) {
        int n = idx >> 5, k4 = (idx & 31) * 4;
        float4 v = *(const float4*)&Wh2[(size_t)n * 128 + k4];
        *(uint2*)(smraw + PO_W2 + n * RS + k4 * 2) = pack_bf16x4(v);
    }
    for (int k = tid; k < 128; k += 512) {
        b1s[k] = bh1[k];
        b2s[k] = bh2[k];
    }
    __syncthreads();

    const int m0 = rg * 16;
    const int arow = m0 + (lane & 7) + ((lane >> 3) & 1) * 8;
    const uint32_t a1_base = smem_u32 + PO_A + (uint32_t)arow * RS2 + ((lane >> 4) & 1) * 16;
    const uint32_t a2_base = smem_u32 + PO_U + (uint32_t)arow * RS  + ((lane >> 4) & 1) * 16;
    const uint32_t b14_base = smem_u32 + PO_W1
                            + (uint32_t)((lane & 7) + ((lane >> 4) & 1) * 8) * RS2
                            + ((lane >> 3) & 1) * 16;
    const uint32_t b24_base = smem_u32 + PO_W2
                            + (uint32_t)((lane & 7) + ((lane >> 4) & 1) * 8) * RS
                            + ((lane >> 3) & 1) * 16;

    const int tig = lane & 3, grp = lane >> 2;
    const int ntiles = (NN + 127) / 128;

    for (int tile = blockIdx.x; tile < ntiles; tile += gridDim.x) {
        const int base = tile * 128;
        __syncthreads();
        for (int idx = tid; idx < 128 * 32; idx += 512) {
            int r = idx >> 5, j4 = (idx & 31) * 4;
            int node = base + r;
            float4 vh = (node < NN) ? *(const float4*)&h[(size_t)node * DH + j4]
                                    : make_float4(0.f, 0.f, 0.f, 0.f);
            float4 vm = (node < NN) ? *(const float4*)&g_msg[(size_t)node * DM + j4]
                                    : make_float4(0.f, 0.f, 0.f, 0.f);
            *(uint2*)(smraw + PO_A + r * RS2 + j4 * 2)         = pack_bf16x4(vh);
            *(uint2*)(smraw + PO_A + r * RS2 + 256 + j4 * 2)   = pack_bf16x4(vm);
        }
        __syncthreads();

        float acc[8][4];
#pragma unroll
        for (int nt = 0; nt < 8; nt++)
#pragma unroll
            for (int r = 0; r < 4; r++) acc[nt][r] = 0.f;
#pragma unroll
        for (int k = 0; k < 16; k++) {
            uint32_t a[4];
            ldmatrix_x4(a[0], a[1], a[2], a[3], a1_base + (uint32_t)k * 32);
#pragma unroll
            for (int p = 0; p < 4; p++) {
                uint32_t b4[4];
                ldmatrix_x4(b4[0], b4[1], b4[2], b4[3],
                            b14_base + (uint32_t)(nh * 4 + p) * (16 * RS2) + (uint32_t)k * 32);
                mma_bf16(acc[2 * p],     a, b4,     acc[2 * p]);
                mma_bf16(acc[2 * p + 1], a, b4 + 2, acc[2 * p + 1]);
            }
        }
#pragma unroll
        for (int ntl = 0; ntl < 8; ntl++) {
            const int c0 = (nh * 8 + ntl) * 8 + tig * 2;
            float2 bb = *(float2*)&b1s[c0];
            uint32_t q0 = silu_bf16x2(acc[ntl][0] + bb.x, acc[ntl][1] + bb.y);
            uint32_t q1 = silu_bf16x2(acc[ntl][2] + bb.x, acc[ntl][3] + bb.y);
            *(uint32_t*)(smraw + PO_U + (m0 + grp) * RS + c0 * 2)     = q0;
            *(uint32_t*)(smraw + PO_U + (m0 + grp + 8) * RS + c0 * 2) = q1;
        }
        __syncthreads();

#pragma unroll
        for (int nt = 0; nt < 8; nt++)
#pragma unroll
            for (int r = 0; r < 4; r++) acc[nt][r] = 0.f;
#pragma unroll
        for (int k = 0; k < 8; k++) {
            uint32_t a[4];
            ldmatrix_x4(a[0], a[1], a[2], a[3], a2_base + (uint32_t)k * 32);
#pragma unroll
            for (int p = 0; p < 4; p++) {
                uint32_t b4[4];
                ldmatrix_x4(b4[0], b4[1], b4[2], b4[3],
                            b24_base + (uint32_t)(nh * 4 + p) * (16 * RS) + (uint32_t)k * 32);
                mma_bf16(acc[2 * p],     a, b4,     acc[2 * p]);
                mma_bf16(acc[2 * p + 1], a, b4 + 2, acc[2 * p + 1]);
            }
        }

        const int node0 = base + m0 + grp;
        const int node1 = node0 + 8;
#pragma unroll
        for (int ntl = 0; ntl < 8; ntl++) {
            const int c0 = (nh * 8 + ntl) * 8 + tig * 2;
            float2 bb = *(float2*)&b2s[c0];
            if (node0 < NN) {
                float2 hv = *(const float2*)&h[(size_t)node0 * DH + c0];
                *(float2*)&out[(size_t)node0 * DH + c0] =
                    make_float2(hv.x + acc[ntl][0] + bb.x, hv.y + acc[ntl][1] + bb.y);
            }
            if (node1 < NN) {
                float2 hv = *(const float2*)&h[(size_t)node1 * DH + c0];
                *(float2*)&out[(size_t)node1 * DH + c0] =
                    make_float2(hv.x + acc[ntl][2] + bb.x, hv.y + acc[ntl][3] + bb.y);
            }
        }
    }
}

// ---------------------------------------------------------------------------
extern "C" void kernel_launch(void* const* d_in, const int* in_sizes, int n_in,
                              void* d_out, int out_size) {
    const float* x   = (const float*)d_in[0];
    const float* h   = (const float*)d_in[1];
    const float* ea  = (const float*)d_in[2];
    const float* We1 = (const float*)d_in[3];
    const float* be1 = (const float*)d_in[4];
    const float* We2 = (const float*)d_in[5];
    const float* be2 = (const float*)d_in[6];
    const float* Wh1 = (const float*)d_in[7];
    const float* bh1 = (const float*)d_in[8];
    const float* Wh2 = (const float*)d_in[9];
    const float* bh2 = (const float*)d_in[10];
    const float* Wa  = (const float*)d_in[11];
    const float* ba  = (const float*)d_in[12];
    const int*   ei  = (const int*)d_in[13];   // int32
    float* out = (float*)d_out;

    cudaFuncSetAttribute(node_pre_kernel,
                         cudaFuncAttributeMaxDynamicSharedMemorySize, NP_TOTAL);
    cudaFuncSetAttribute(edge_kernel,
                         cudaFuncAttributeMaxDynamicSharedMemorySize, EB_TOTAL);
    cudaFuncSetAttribute(node_post_kernel,
                         cudaFuncAttributeMaxDynamicSharedMemorySize, PO_TOTAL);

    node_pre_kernel<<<296, 256, NP_TOTAL>>>(h, We1);   // also zeroes g_msg
    edge_kernel<<<296, 256, EB_TOTAL>>>(x, ea, We1, be1, We2, be2, Wa, ba, ei);
    node_post_kernel<<<148, 512, PO_TOTAL>>>(h, Wh1, bh1, Wh2, bh2, out);
}